// round 1
// baseline (speedup 1.0000x reference)
#include <cuda_runtime.h>
#include <cuda_bf16.h>
#include <math.h>

// ---------------- problem constants ----------------
#define BB 64
#define TT 243
#define JJ 17
#define DD 256
#define DH 128
#define TR 60
#define KSEL 30
#define MROWS (BB*TT*JJ)       // 264384
#define TJ (TT*JJ)             // 4131

// ---------------- scratch (device globals; no allocs allowed) ----------------
__device__ float g_h[(size_t)MROWS*DD];          // 270.7 MB: fp-stage output
__device__ float g_xd[(size_t)BB*TR*JJ*DD];      // 66.8 MB: pooled (L2-resident)
__device__ float g_pm[(size_t)BB*TR*DD];         // pooled mean over J
__device__ float g_mean1[MROWS], g_rstd1[MROWS]; // LN stats of x rows
__device__ float g_mean2[MROWS], g_rstd2[MROWS]; // LN stats of up rows
__device__ int   g_off0[MROWS], g_off1[MROWS];   // gather offsets into g_xd
__device__ float g_wlerp[MROWS];                 // lerp weight per row
__device__ int   g_topidx[BB*KSEL];

__device__ __forceinline__ float gelu_f(float x) {
    return 0.5f * x * (1.0f + erff(x * 0.70710678118654752f));
}

// ---------------- K0: per-row LN stats of x ----------------
__global__ __launch_bounds__(256) void row_stats_x(const float* __restrict__ X) {
    int row = blockIdx.x * 8 + (threadIdx.x >> 5);
    int lane = threadIdx.x & 31;
    const float* p = X + (size_t)row * DD;
    float4 v0 = *(const float4*)(p + lane * 4);
    float4 v1 = *(const float4*)(p + 128 + lane * 4);
    float s  = v0.x + v0.y + v0.z + v0.w + v1.x + v1.y + v1.z + v1.w;
    float ss = v0.x*v0.x + v0.y*v0.y + v0.z*v0.z + v0.w*v0.w
             + v1.x*v1.x + v1.y*v1.y + v1.z*v1.z + v1.w*v1.w;
    #pragma unroll
    for (int o = 16; o > 0; o >>= 1) {
        s  += __shfl_xor_sync(0xffffffffu, s,  o);
        ss += __shfl_xor_sync(0xffffffffu, ss, o);
    }
    if (lane == 0) {
        float mu = s * (1.0f / DD);
        float var = ss * (1.0f / DD) - mu * mu;
        g_mean1[row] = mu;
        g_rstd1[row] = rsqrtf(var + 1e-5f);
    }
}

// ---------------- fused LN + GEMM(256x256) + bias + GELU (+residual) ----------------
// MODE 0: A row = LN(x_row)*g+b          -> out = gelu(A@W + bias)        (writes g_h)
// MODE 1: A row = LN(lerp(xd,xd))*g+b    -> out = gelu(A@W + bias) + x    (writes d_out)
template <int MODE>
__global__ __launch_bounds__(256) void gemm_fused(
    const float* __restrict__ X,       // x (MODE0: A source, MODE1: residual)
    const float* __restrict__ W,       // [256,256] row-major
    const float* __restrict__ bias,    // [256]
    const float* __restrict__ ln_g,    // [256]
    const float* __restrict__ ln_b,    // [256]
    float* __restrict__ out)
{
    __shared__ float As[32][68];    // [k][m], padded
    __shared__ float Bs[32][256];   // [k][n]

    const int tid  = threadIdx.x;
    const int m0   = blockIdx.x * 64;
    const int trow = tid >> 5;      // 0..7
    const int tcol = tid & 31;      // 0..31

    float acc[8][8];
    #pragma unroll
    for (int i = 0; i < 8; i++)
        #pragma unroll
        for (int j = 0; j < 8; j++) acc[i][j] = 0.0f;

    for (int kt = 0; kt < 256; kt += 32) {
        // --- stage A tile (64 rows x 32 k), LN applied on the fly ---
        #pragma unroll
        for (int it = 0; it < 2; ++it) {
            int f   = tid + it * 256;   // 0..511
            int row = f >> 3;           // 0..63
            int fc  = f & 7;            // 0..7
            int k   = kt + fc * 4;
            int m   = m0 + row;
            float4 v;
            float mu, rs;
            if (MODE == 0) {
                v  = *(const float4*)(X + (size_t)m * DD + k);
                mu = g_mean1[m]; rs = g_rstd1[m];
            } else {
                float w = g_wlerp[m];
                float4 a  = *(const float4*)(g_xd + g_off0[m] + k);
                float4 bq = *(const float4*)(g_xd + g_off1[m] + k);
                v.x = a.x * (1.0f - w) + bq.x * w;
                v.y = a.y * (1.0f - w) + bq.y * w;
                v.z = a.z * (1.0f - w) + bq.z * w;
                v.w = a.w * (1.0f - w) + bq.w * w;
                mu = g_mean2[m]; rs = g_rstd2[m];
            }
            float4 gg = *(const float4*)(ln_g + k);
            float4 bb = *(const float4*)(ln_b + k);
            As[fc*4+0][row] = (v.x - mu) * rs * gg.x + bb.x;
            As[fc*4+1][row] = (v.y - mu) * rs * gg.y + bb.y;
            As[fc*4+2][row] = (v.z - mu) * rs * gg.z + bb.z;
            As[fc*4+3][row] = (v.w - mu) * rs * gg.w + bb.w;
        }
        // --- stage B tile (32 k x 256 n) ---
        #pragma unroll
        for (int it = 0; it < 8; ++it) {
            int f  = tid + it * 256;    // 0..2047 (float4 units)
            int kl = f >> 6;            // 0..31
            int n4 = f & 63;            // 0..63
            *(float4*)&Bs[kl][n4 * 4] =
                *(const float4*)(W + (size_t)(kt + kl) * DD + n4 * 4);
        }
        __syncthreads();
        // --- 8x8 microkernel ---
        #pragma unroll
        for (int kk = 0; kk < 32; ++kk) {
            float4 a0 = *(const float4*)&As[kk][trow * 8];
            float4 a1 = *(const float4*)&As[kk][trow * 8 + 4];
            float4 b0 = *(const float4*)&Bs[kk][tcol * 4];
            float4 b1 = *(const float4*)&Bs[kk][tcol * 4 + 128];
            float a[8] = {a0.x,a0.y,a0.z,a0.w,a1.x,a1.y,a1.z,a1.w};
            float b[8] = {b0.x,b0.y,b0.z,b0.w,b1.x,b1.y,b1.z,b1.w};
            #pragma unroll
            for (int i = 0; i < 8; i++)
                #pragma unroll
                for (int j = 0; j < 8; j++) acc[i][j] = fmaf(a[i], b[j], acc[i][j]);
        }
        __syncthreads();
    }

    // --- epilogue: bias + gelu (+residual), cols {tcol*4, tcol*4+128} ---
    const int n0 = tcol * 4, n1 = tcol * 4 + 128;
    float4 bia0 = *(const float4*)(bias + n0);
    float4 bia1 = *(const float4*)(bias + n1);
    #pragma unroll
    for (int r = 0; r < 8; r++) {
        int m = m0 + trow * 8 + r;
        float o0 = gelu_f(acc[r][0] + bia0.x);
        float o1 = gelu_f(acc[r][1] + bia0.y);
        float o2 = gelu_f(acc[r][2] + bia0.z);
        float o3 = gelu_f(acc[r][3] + bia0.w);
        float o4 = gelu_f(acc[r][4] + bia1.x);
        float o5 = gelu_f(acc[r][5] + bia1.y);
        float o6 = gelu_f(acc[r][6] + bia1.z);
        float o7 = gelu_f(acc[r][7] + bia1.w);
        if (MODE == 1) {
            float4 x0v = *(const float4*)(X + (size_t)m * DD + n0);
            float4 x1v = *(const float4*)(X + (size_t)m * DD + n1);
            o0 += x0v.x; o1 += x0v.y; o2 += x0v.z; o3 += x0v.w;
            o4 += x1v.x; o5 += x1v.y; o6 += x1v.z; o7 += x1v.w;
        }
        float4 w0 = make_float4(o0, o1, o2, o3);
        float4 w1 = make_float4(o4, o5, o6, o7);
        *(float4*)(out + (size_t)m * DD + n0) = w0;
        *(float4*)(out + (size_t)m * DD + n1) = w1;
    }
}

// ---------------- K2a: adaptive avg pool T -> T_RED (overlapping bins) ----------------
__global__ __launch_bounds__(256) void pool_kernel() {
    int id = blockIdx.x;               // b * TR * JJ + r * JJ + j
    int j = id % JJ;
    int r = (id / JJ) % TR;
    int b = id / (JJ * TR);
    int s = (r * TT) / TR;
    int e = ((r + 1) * TT + TR - 1) / TR;
    int c = threadIdx.x;
    float acc = 0.0f;
    for (int t = s; t < e; ++t)
        acc += g_h[((size_t)((b * TT + t) * JJ + j)) * DD + c];
    g_xd[((size_t)((b * TR + r) * JJ + j)) * DD + c] = acc / (float)(e - s);
}

// ---------------- K2b: mean over J ----------------
__global__ __launch_bounds__(256) void pooled_mean_kernel() {
    int id = blockIdx.x;               // b * TR + r
    int c = threadIdx.x;
    float acc = 0.0f;
    #pragma unroll
    for (int j = 0; j < JJ; ++j)
        acc += g_xd[((size_t)(id * JJ + j)) * DD + c];
    g_pm[(size_t)id * DD + c] = acc * (1.0f / JJ);
}

// ---------------- K3: scorer + top-k (one block per batch) ----------------
__global__ __launch_bounds__(128) void scorer_topk(
    const float* __restrict__ w1, const float* __restrict__ b1,
    const float* __restrict__ w2, const float* __restrict__ b2)
{
    __shared__ float spm[DD];
    __shared__ float red[DH];
    __shared__ float scores[TR];
    __shared__ int   sel[TR];
    int b = blockIdx.x, tid = threadIdx.x;

    for (int r = 0; r < TR; ++r) {
        spm[tid]        = g_pm[((size_t)(b * TR + r)) * DD + tid];
        spm[tid + 128]  = g_pm[((size_t)(b * TR + r)) * DD + tid + 128];
        __syncthreads();
        float acc = b1[tid];
        #pragma unroll 8
        for (int c = 0; c < DD; ++c)
            acc = fmaf(spm[c], w1[c * DH + tid], acc);
        red[tid] = gelu_f(acc) * w2[tid];
        __syncthreads();
        #pragma unroll
        for (int s = 64; s > 0; s >>= 1) {
            if (tid < s) red[tid] += red[tid + s];
            __syncthreads();
        }
        if (tid == 0)
            scores[r] = 1.0f / (1.0f + expf(-(red[0] + b2[0])));
        __syncthreads();
    }
    if (tid < TR) {
        float s = scores[tid];
        int rank = 0;
        for (int q = 0; q < TR; ++q) {
            float sq = scores[q];
            rank += (sq > s) || (sq == s && q < tid);
        }
        sel[tid] = (rank < KSEL) ? 1 : 0;
    }
    __syncthreads();
    if (tid == 0) {
        int pos = 0;
        for (int r = 0; r < TR; ++r)
            if (sel[r]) g_topidx[b * KSEL + (pos++)] = r;
    }
}

// ---------------- K4pre: per-row lerp offsets/weight + LN stats of 'up' ----------------
__global__ __launch_bounds__(256) void up_pre() {
    int row  = blockIdx.x * 8 + (threadIdx.x >> 5);
    int lane = threadIdx.x & 31;
    int b   = row / TJ;
    int rem = row % TJ;
    int t = rem / JJ;
    int j = rem % JJ;

    const float scale = (float)(30.0 / 243.0);
    float src = (t + 0.5f) * scale - 0.5f;
    src = fminf(fmaxf(src, 0.0f), (float)(KSEL - 1));
    int x0 = (int)src;                     // src >= 0 -> trunc == floor
    int x1 = min(x0 + 1, KSEL - 1);
    float w = src - (float)x0;
    int i0 = g_topidx[b * KSEL + x0];
    int i1 = g_topidx[b * KSEL + x1];
    int off0 = ((b * TR + i0) * JJ + j) * DD;
    int off1 = ((b * TR + i1) * JJ + j) * DD;

    float s = 0.0f, ss = 0.0f;
    #pragma unroll
    for (int h = 0; h < 2; ++h) {
        int c = h * 128 + lane * 4;
        float4 a  = *(const float4*)(g_xd + off0 + c);
        float4 bq = *(const float4*)(g_xd + off1 + c);
        float v0 = a.x * (1.0f - w) + bq.x * w;
        float v1 = a.y * (1.0f - w) + bq.y * w;
        float v2 = a.z * (1.0f - w) + bq.z * w;
        float v3 = a.w * (1.0f - w) + bq.w * w;
        s  += v0 + v1 + v2 + v3;
        ss += v0*v0 + v1*v1 + v2*v2 + v3*v3;
    }
    #pragma unroll
    for (int o = 16; o > 0; o >>= 1) {
        s  += __shfl_xor_sync(0xffffffffu, s,  o);
        ss += __shfl_xor_sync(0xffffffffu, ss, o);
    }
    if (lane == 0) {
        float mu  = s * (1.0f / DD);
        float var = ss * (1.0f / DD) - mu * mu;
        g_mean2[row] = mu;
        g_rstd2[row] = rsqrtf(var + 1e-5f);
        g_off0[row] = off0;
        g_off1[row] = off1;
        g_wlerp[row] = w;
    }
}

// ---------------- launch ----------------
extern "C" void kernel_launch(void* const* d_in, const int* in_sizes, int n_in,
                              void* d_out, int out_size) {
    const float* x       = (const float*)d_in[0];
    const float* fp_g    = (const float*)d_in[1];
    const float* fp_b    = (const float*)d_in[2];
    const float* fp_w    = (const float*)d_in[3];
    const float* fp_bias = (const float*)d_in[4];
    const float* sc_w1   = (const float*)d_in[5];
    const float* sc_b1   = (const float*)d_in[6];
    const float* sc_w2   = (const float*)d_in[7];
    const float* sc_b2   = (const float*)d_in[8];
    const float* op_g    = (const float*)d_in[9];
    const float* op_b    = (const float*)d_in[10];
    const float* op_w    = (const float*)d_in[11];
    const float* op_bias = (const float*)d_in[12];
    float* out = (float*)d_out;

    float* h_ptr;
    cudaGetSymbolAddress((void**)&h_ptr, g_h);  // query only, no allocation

    row_stats_x<<<MROWS / 8, 256>>>(x);
    gemm_fused<0><<<MROWS / 64, 256>>>(x, fp_w, fp_bias, fp_g, fp_b, h_ptr);
    pool_kernel<<<BB * TR * JJ, 256>>>();
    pooled_mean_kernel<<<BB * TR, 256>>>();
    scorer_topk<<<BB, 128>>>(sc_w1, sc_b1, sc_w2, sc_b2);
    up_pre<<<MROWS / 8, 256>>>();
    gemm_fused<1><<<MROWS / 64, 256>>>(x, op_w, op_bias, op_g, op_b, out);
}

// round 3
// speedup vs baseline: 1.5433x; 1.5433x over previous
#include <cuda_runtime.h>
#include <cuda_bf16.h>
#include <math.h>
#include <stdint.h>

// ---------------- problem constants ----------------
#define BB 64
#define TT 243
#define JJ 17
#define DD 256
#define DH 128
#define TR 60
#define KSEL 30
#define MROWS (BB*TT*JJ)       // 264384
#define TJ (TT*JJ)             // 4131
#define MTILES ((MROWS + 127) / 128)   // 2066

// ---------------- scratch (device globals; no allocs allowed) ----------------
__device__ float g_h[(size_t)MROWS*DD];          // 270.7 MB: fp-stage output
__device__ float g_xd[(size_t)BB*TR*JJ*DD];      // 66.8 MB: pooled
__device__ float g_pm[(size_t)BB*TR*DD];         // pooled mean over J
__device__ float g_mean1[MROWS], g_rstd1[MROWS]; // LN stats of x rows
__device__ float g_mean2[MROWS], g_rstd2[MROWS]; // LN stats of up rows
__device__ int   g_off0[MROWS], g_off1[MROWS];   // gather offsets into g_xd
__device__ float g_wlerp[MROWS];                 // lerp weight per row
__device__ int   g_topidx[BB*KSEL];
__device__ float g_wt0h[DD*DD], g_wt0l[DD*DD];   // fp_w transposed, tf32 hi/lo
__device__ float g_wt1h[DD*DD], g_wt1l[DD*DD];   // op_w transposed, tf32 hi/lo

__device__ __forceinline__ float tf32_rna(float x) {
    float r; asm("cvt.rna.tf32.f32 %0, %1;" : "=f"(r) : "f"(x)); return r;
}
__device__ __forceinline__ float gelu_f(float x) {
    return 0.5f * x * (1.0f + erff(x * 0.70710678118654752f));
}
// mma.sync m16n8k8 tf32 (sm_80+, no "a"-suffix features)
__device__ __forceinline__ void mma1688(float* d, const float* a, const float* b) {
    asm volatile(
        "mma.sync.aligned.m16n8k8.row.col.f32.tf32.tf32.f32 "
        "{%0,%1,%2,%3}, {%4,%5,%6,%7}, {%8,%9}, {%0,%1,%2,%3};"
        : "+f"(d[0]), "+f"(d[1]), "+f"(d[2]), "+f"(d[3])
        : "r"(__float_as_uint(a[0])), "r"(__float_as_uint(a[1])),
          "r"(__float_as_uint(a[2])), "r"(__float_as_uint(a[3])),
          "r"(__float_as_uint(b[0])), "r"(__float_as_uint(b[1])));
}

#define APAD 36   // smem row stride (floats) for 32-float rows (+4 pad)

// ---------------- K0: per-row LN stats of x ----------------
__global__ __launch_bounds__(256) void row_stats_x(const float* __restrict__ X) {
    int row = blockIdx.x * 8 + (threadIdx.x >> 5);
    int lane = threadIdx.x & 31;
    const float* p = X + (size_t)row * DD;
    float4 v0 = *(const float4*)(p + lane * 4);
    float4 v1 = *(const float4*)(p + 128 + lane * 4);
    float s  = v0.x + v0.y + v0.z + v0.w + v1.x + v1.y + v1.z + v1.w;
    float ss = v0.x*v0.x + v0.y*v0.y + v0.z*v0.z + v0.w*v0.w
             + v1.x*v1.x + v1.y*v1.y + v1.z*v1.z + v1.w*v1.w;
    #pragma unroll
    for (int o = 16; o > 0; o >>= 1) {
        s  += __shfl_xor_sync(0xffffffffu, s,  o);
        ss += __shfl_xor_sync(0xffffffffu, ss, o);
    }
    if (lane == 0) {
        float mu = s * (1.0f / DD);
        float var = ss * (1.0f / DD) - mu * mu;
        g_mean1[row] = mu;
        g_rstd1[row] = rsqrtf(var + 1e-5f);
    }
}

// ---------------- weight prep: transpose + tf32 hi/lo split ----------------
__global__ __launch_bounds__(256) void prep_w(const float* __restrict__ W,
                                              float* __restrict__ Wh,
                                              float* __restrict__ Wl) {
    int idx = blockIdx.x * 256 + threadIdx.x;   // 65536
    int k = idx >> 8, n = idx & 255;
    float w = W[idx];                            // W[k][n]
    float hi = tf32_rna(w);
    float lo = tf32_rna(w - hi);
    Wh[n * DD + k] = hi;
    Wl[n * DD + k] = lo;
}

// ---------------- mma.sync GEMM: LN(A) @ W^T + bias -> gelu (+residual) ----------------
// MODE 0: A = LN(x_row),    out = gelu(.)        X3=1 (tf32x3 compensated)
// MODE 1: A = LN(lerp(xd)), out = gelu(.) + x    X3=0 (single tf32)
// CTA: 256 thr (8 warps, 4x2), tile 128(M) x 128(N), K chunks of 32.
template <int MODE, int X3>
__global__ __launch_bounds__(256, 2) void gemm_mma(
    const float* __restrict__ X,
    const float* __restrict__ Wh, const float* __restrict__ Wl,
    const float* __restrict__ bias,
    const float* __restrict__ ln_g, const float* __restrict__ ln_b,
    float* __restrict__ out)
{
    extern __shared__ float smem[];
    float* sAh = smem;                                 // [128][APAD]
    float* sAl = smem + 128 * APAD;                    // X3 only
    float* sBh = smem + (X3 ? 2 : 1) * 128 * APAD;     // [128][APAD]
    float* sBl = smem + 3 * 128 * APAD;                // X3 only

    const int tid  = threadIdx.x;
    const int wid  = tid >> 5;
    const int lane = tid & 31;
    const int m0   = blockIdx.x * 128;
    const int n0   = blockIdx.y * 128;
    const int warp_m = (wid & 3) * 32;
    const int warp_n = (wid >> 2) * 64;
    const int r  = lane >> 2;      // 0..7
    const int cq = lane & 3;       // 0..3

    float acc[2][8][4];
    #pragma unroll
    for (int i = 0; i < 2; i++)
        #pragma unroll
        for (int j = 0; j < 8; j++)
            #pragma unroll
            for (int q = 0; q < 4; q++) acc[i][j][q] = 0.0f;

    // per-thread smem fragment base pointers
    const float* paAh = sAh + (warp_m + r) * APAD + cq;
    const float* paAl = sAl + (warp_m + r) * APAD + cq;
    const float* paBh = sBh + (warp_n + r) * APAD + cq;
    const float* paBl = sBl + (warp_n + r) * APAD + cq;

    for (int c = 0; c < 8; ++c) {
        const int kt = c * 32;
        // ---- stage A chunk: 128 rows x 32 k, LN fused, tf32 convert ----
        #pragma unroll
        for (int it = 0; it < 4; ++it) {
            int f   = tid + it * 256;     // 0..1023
            int row = f >> 3;             // 0..127
            int fc  = f & 7;              // 0..7
            int k   = kt + fc * 4;
            int m   = min(m0 + row, MROWS - 1);
            float4 v; float mu, rs;
            if (MODE == 0) {
                v = *(const float4*)(X + (size_t)m * DD + k);
                mu = g_mean1[m]; rs = g_rstd1[m];
            } else {
                float w = g_wlerp[m];
                float4 a  = *(const float4*)(g_xd + g_off0[m] + k);
                float4 bq = *(const float4*)(g_xd + g_off1[m] + k);
                v.x = a.x + (bq.x - a.x) * w;
                v.y = a.y + (bq.y - a.y) * w;
                v.z = a.z + (bq.z - a.z) * w;
                v.w = a.w + (bq.w - a.w) * w;
                mu = g_mean2[m]; rs = g_rstd2[m];
            }
            float4 gg = *(const float4*)(ln_g + k);
            float4 bb = *(const float4*)(ln_b + k);
            float a0 = (v.x - mu) * rs * gg.x + bb.x;
            float a1 = (v.y - mu) * rs * gg.y + bb.y;
            float a2 = (v.z - mu) * rs * gg.z + bb.z;
            float a3 = (v.w - mu) * rs * gg.w + bb.w;
            float h0 = tf32_rna(a0), h1 = tf32_rna(a1);
            float h2 = tf32_rna(a2), h3 = tf32_rna(a3);
            float* dst = sAh + row * APAD + fc * 4;
            dst[0] = h0; dst[1] = h1; dst[2] = h2; dst[3] = h3;
            if (X3) {
                float* dl = sAl + row * APAD + fc * 4;
                dl[0] = tf32_rna(a0 - h0); dl[1] = tf32_rna(a1 - h1);
                dl[2] = tf32_rna(a2 - h2); dl[3] = tf32_rna(a3 - h3);
            }
        }
        // ---- stage B chunk: 128 n-rows x 32 k (already tf32) ----
        #pragma unroll
        for (int it = 0; it < 4; ++it) {
            int f  = tid + it * 256;
            int nl = f >> 3;
            int fc = f & 7;
            int ng = n0 + nl;
            *(float4*)(sBh + nl * APAD + fc * 4) =
                *(const float4*)(Wh + (size_t)ng * DD + kt + fc * 4);
            if (X3)
                *(float4*)(sBl + nl * APAD + fc * 4) =
                    *(const float4*)(Wl + (size_t)ng * DD + kt + fc * 4);
        }
        __syncthreads();

        // ---- compute: 4 k-steps of 8 ----
        #pragma unroll
        for (int ks = 0; ks < 4; ++ks) {
            const int ko = ks * 8;
            float ah[2][4], al[2][4];
            #pragma unroll
            for (int mt = 0; mt < 2; ++mt) {
                const float* p = paAh + mt * 16 * APAD + ko;
                ah[mt][0] = p[0];
                ah[mt][1] = p[8 * APAD];
                ah[mt][2] = p[4];
                ah[mt][3] = p[8 * APAD + 4];
                if (X3) {
                    const float* q = paAl + mt * 16 * APAD + ko;
                    al[mt][0] = q[0];
                    al[mt][1] = q[8 * APAD];
                    al[mt][2] = q[4];
                    al[mt][3] = q[8 * APAD + 4];
                }
            }
            #pragma unroll
            for (int nt = 0; nt < 8; ++nt) {
                float bh[2];
                const float* pb = paBh + nt * 8 * APAD + ko;
                bh[0] = pb[0]; bh[1] = pb[4];
                mma1688(acc[0][nt], ah[0], bh);
                mma1688(acc[1][nt], ah[1], bh);
                if (X3) {
                    mma1688(acc[0][nt], al[0], bh);
                    mma1688(acc[1][nt], al[1], bh);
                    float bl[2];
                    const float* pl = paBl + nt * 8 * APAD + ko;
                    bl[0] = pl[0]; bl[1] = pl[4];
                    mma1688(acc[0][nt], ah[0], bl);
                    mma1688(acc[1][nt], ah[1], bl);
                }
            }
        }
        __syncthreads();
    }

    // ---- epilogue: bias + gelu (+residual) -> gmem (float2 stores) ----
    #pragma unroll
    for (int mt = 0; mt < 2; ++mt) {
        int mrow = m0 + warp_m + mt * 16 + r;
        #pragma unroll
        for (int nt = 0; nt < 8; ++nt) {
            int n = n0 + warp_n + nt * 8 + 2 * cq;
            float2 bi = *(const float2*)(bias + n);
            // rows mrow and mrow+8
            if (mrow < MROWS) {
                float o0 = gelu_f(acc[mt][nt][0] + bi.x);
                float o1 = gelu_f(acc[mt][nt][1] + bi.y);
                if (MODE == 1) {
                    float2 xr = *(const float2*)(X + (size_t)mrow * DD + n);
                    o0 += xr.x; o1 += xr.y;
                }
                *(float2*)(out + (size_t)mrow * DD + n) = make_float2(o0, o1);
            }
            int mrow2 = mrow + 8;
            if (mrow2 < MROWS) {
                float o2 = gelu_f(acc[mt][nt][2] + bi.x);
                float o3 = gelu_f(acc[mt][nt][3] + bi.y);
                if (MODE == 1) {
                    float2 xr = *(const float2*)(X + (size_t)mrow2 * DD + n);
                    o2 += xr.x; o3 += xr.y;
                }
                *(float2*)(out + (size_t)mrow2 * DD + n) = make_float2(o2, o3);
            }
        }
    }
}

// ---------------- K2a: adaptive avg pool T -> T_RED (overlapping bins) ----------------
__global__ __launch_bounds__(256) void pool_kernel() {
    int id = blockIdx.x;               // b * TR * JJ + r * JJ + j
    int j = id % JJ;
    int r = (id / JJ) % TR;
    int b = id / (JJ * TR);
    int s = (r * TT) / TR;
    int e = ((r + 1) * TT + TR - 1) / TR;
    int c = threadIdx.x;
    float acc = 0.0f;
    for (int t = s; t < e; ++t)
        acc += g_h[((size_t)((b * TT + t) * JJ + j)) * DD + c];
    g_xd[((size_t)((b * TR + r) * JJ + j)) * DD + c] = acc / (float)(e - s);
}

// ---------------- K2b: mean over J ----------------
__global__ __launch_bounds__(256) void pooled_mean_kernel() {
    int id = blockIdx.x;               // b * TR + r
    int c = threadIdx.x;
    float acc = 0.0f;
    #pragma unroll
    for (int j = 0; j < JJ; ++j)
        acc += g_xd[((size_t)(id * JJ + j)) * DD + c];
    g_pm[(size_t)id * DD + c] = acc * (1.0f / JJ);
}

// ---------------- K3: scorer + top-k (one block per batch) ----------------
__global__ __launch_bounds__(128) void scorer_topk(
    const float* __restrict__ w1, const float* __restrict__ b1,
    const float* __restrict__ w2, const float* __restrict__ b2)
{
    __shared__ float spm[DD];
    __shared__ float red[DH];
    __shared__ float scores[TR];
    __shared__ int   sel[TR];
    int b = blockIdx.x, tid = threadIdx.x;

    for (int r = 0; r < TR; ++r) {
        spm[tid]        = g_pm[((size_t)(b * TR + r)) * DD + tid];
        spm[tid + 128]  = g_pm[((size_t)(b * TR + r)) * DD + tid + 128];
        __syncthreads();
        float acc = b1[tid];
        #pragma unroll 8
        for (int c = 0; c < DD; ++c)
            acc = fmaf(spm[c], w1[c * DH + tid], acc);
        red[tid] = gelu_f(acc) * w2[tid];
        __syncthreads();
        #pragma unroll
        for (int s = 64; s > 0; s >>= 1) {
            if (tid < s) red[tid] += red[tid + s];
            __syncthreads();
        }
        if (tid == 0)
            scores[r] = 1.0f / (1.0f + expf(-(red[0] + b2[0])));
        __syncthreads();
    }
    if (tid < TR) {
        float s = scores[tid];
        int rank = 0;
        for (int q = 0; q < TR; ++q) {
            float sq = scores[q];
            rank += (sq > s) || (sq == s && q < tid);
        }
        sel[tid] = (rank < KSEL) ? 1 : 0;
    }
    __syncthreads();
    if (tid == 0) {
        int pos = 0;
        for (int r = 0; r < TR; ++r)
            if (sel[r]) g_topidx[b * KSEL + (pos++)] = r;
    }
}

// ---------------- K4pre: per-row lerp offsets/weight + LN stats of 'up' ----------------
__global__ __launch_bounds__(256) void up_pre() {
    int row  = blockIdx.x * 8 + (threadIdx.x >> 5);
    int lane = threadIdx.x & 31;
    int b   = row / TJ;
    int rem = row % TJ;
    int t = rem / JJ;
    int j = rem % JJ;

    const float scale = (float)(30.0 / 243.0);
    float src = (t + 0.5f) * scale - 0.5f;
    src = fminf(fmaxf(src, 0.0f), (float)(KSEL - 1));
    int x0 = (int)src;
    int x1 = min(x0 + 1, KSEL - 1);
    float w = src - (float)x0;
    int i0 = g_topidx[b * KSEL + x0];
    int i1 = g_topidx[b * KSEL + x1];
    int off0 = ((b * TR + i0) * JJ + j) * DD;
    int off1 = ((b * TR + i1) * JJ + j) * DD;

    float s = 0.0f, ss = 0.0f;
    #pragma unroll
    for (int h = 0; h < 2; ++h) {
        int c = h * 128 + lane * 4;
        float4 a  = *(const float4*)(g_xd + off0 + c);
        float4 bq = *(const float4*)(g_xd + off1 + c);
        float v0 = a.x + (bq.x - a.x) * w;
        float v1 = a.y + (bq.y - a.y) * w;
        float v2 = a.z + (bq.z - a.z) * w;
        float v3 = a.w + (bq.w - a.w) * w;
        s  += v0 + v1 + v2 + v3;
        ss += v0*v0 + v1*v1 + v2*v2 + v3*v3;
    }
    #pragma unroll
    for (int o = 16; o > 0; o >>= 1) {
        s  += __shfl_xor_sync(0xffffffffu, s,  o);
        ss += __shfl_xor_sync(0xffffffffu, ss, o);
    }
    if (lane == 0) {
        float mu  = s * (1.0f / DD);
        float var = ss * (1.0f / DD) - mu * mu;
        g_mean2[row] = mu;
        g_rstd2[row] = rsqrtf(var + 1e-5f);
        g_off0[row] = off0;
        g_off1[row] = off1;
        g_wlerp[row] = w;
    }
}

// ---------------- launch ----------------
#define SMEM_X3 (4 * 128 * APAD * 4)   // 73728 B
#define SMEM_X1 (2 * 128 * APAD * 4)   // 36864 B

extern "C" void kernel_launch(void* const* d_in, const int* in_sizes, int n_in,
                              void* d_out, int out_size) {
    const float* x       = (const float*)d_in[0];
    const float* fp_g    = (const float*)d_in[1];
    const float* fp_b    = (const float*)d_in[2];
    const float* fp_w    = (const float*)d_in[3];
    const float* fp_bias = (const float*)d_in[4];
    const float* sc_w1   = (const float*)d_in[5];
    const float* sc_b1   = (const float*)d_in[6];
    const float* sc_w2   = (const float*)d_in[7];
    const float* sc_b2   = (const float*)d_in[8];
    const float* op_g    = (const float*)d_in[9];
    const float* op_b    = (const float*)d_in[10];
    const float* op_w    = (const float*)d_in[11];
    const float* op_bias = (const float*)d_in[12];
    float* out = (float*)d_out;

    float *h_ptr, *w0h, *w0l, *w1h, *w1l;
    cudaGetSymbolAddress((void**)&h_ptr, g_h);
    cudaGetSymbolAddress((void**)&w0h, g_wt0h);
    cudaGetSymbolAddress((void**)&w0l, g_wt0l);
    cudaGetSymbolAddress((void**)&w1h, g_wt1h);
    cudaGetSymbolAddress((void**)&w1l, g_wt1l);

    cudaFuncSetAttribute(gemm_mma<0,1>, cudaFuncAttributeMaxDynamicSharedMemorySize, SMEM_X3);
    cudaFuncSetAttribute(gemm_mma<1,0>, cudaFuncAttributeMaxDynamicSharedMemorySize, SMEM_X1);

    dim3 ggrid(MTILES, 2);
    prep_w<<<256, 256>>>(fp_w, w0h, w0l);
    prep_w<<<256, 256>>>(op_w, w1h, w1l);
    row_stats_x<<<MROWS / 8, 256>>>(x);
    gemm_mma<0,1><<<ggrid, 256, SMEM_X3>>>(x, w0h, w0l, fp_bias, fp_g, fp_b, h_ptr);
    pool_kernel<<<BB * TR * JJ, 256>>>();
    pooled_mean_kernel<<<BB * TR, 256>>>();
    scorer_topk<<<BB, 128>>>(sc_w1, sc_b1, sc_w2, sc_b2);
    up_pre<<<MROWS / 8, 256>>>();
    gemm_mma<1,0><<<ggrid, 256, SMEM_X1>>>(x, w1h, w1l, op_bias, op_g, op_b, out);
}

// round 4
// speedup vs baseline: 1.6837x; 1.0910x over previous
#include <cuda_runtime.h>
#include <cuda_bf16.h>
#include <math.h>
#include <stdint.h>

// ---------------- problem constants ----------------
#define BB 64
#define TT 243
#define JJ 17
#define DD 256
#define DH 128
#define TR 60
#define KSEL 30
#define MROWS (BB*TT*JJ)       // 264384
#define TJ (TT*JJ)             // 4131
#define MTILES ((MROWS + 127) / 128)   // 2066

// ---------------- scratch (device globals; no allocs allowed) ----------------
__device__ float g_h[(size_t)MROWS*DD];          // 270.7 MB: fp-stage output
__device__ float g_xd[(size_t)BB*TR*JJ*DD];      // 66.8 MB: pooled
__device__ float g_pm[(size_t)BB*TR*DD];         // pooled mean over J
__device__ float g_mean1[MROWS], g_rstd1[MROWS]; // LN stats of x rows
__device__ float g_mean2[MROWS], g_rstd2[MROWS]; // LN stats of up rows
__device__ int   g_off0[MROWS], g_off1[MROWS];   // gather offsets into g_xd
__device__ float g_wlerp[MROWS];                 // lerp weight per row
__device__ int   g_topidx[BB*KSEL];
__device__ float g_wt0h[DD*DD], g_wt0l[DD*DD];   // fp_w transposed, tf32 hi/lo
__device__ float g_wt1h[DD*DD], g_wt1l[DD*DD];   // op_w transposed, tf32 hi/lo

__device__ __forceinline__ float tf32_rna(float x) {
    float r; asm("cvt.rna.tf32.f32 %0, %1;" : "=f"(r) : "f"(x)); return r;
}
__device__ __forceinline__ float gelu_f(float x) {
    return 0.5f * x * (1.0f + erff(x * 0.70710678118654752f));
}
__device__ __forceinline__ uint32_t smem_u32(const void* p) {
    uint32_t a;
    asm("{ .reg .u64 t; cvta.to.shared.u64 t, %1; cvt.u32.u64 %0, t; }" : "=r"(a) : "l"(p));
    return a;
}
// mma.sync m16n8k8 tf32 (sm_80+, non-"a" target safe)
__device__ __forceinline__ void mma1688(float* d, const float* a, const float* b) {
    asm volatile(
        "mma.sync.aligned.m16n8k8.row.col.f32.tf32.tf32.f32 "
        "{%0,%1,%2,%3}, {%4,%5,%6,%7}, {%8,%9}, {%0,%1,%2,%3};"
        : "+f"(d[0]), "+f"(d[1]), "+f"(d[2]), "+f"(d[3])
        : "r"(__float_as_uint(a[0])), "r"(__float_as_uint(a[1])),
          "r"(__float_as_uint(a[2])), "r"(__float_as_uint(a[3])),
          "r"(__float_as_uint(b[0])), "r"(__float_as_uint(b[1])));
}
#define CP_ASYNC(dst, src) asm volatile("cp.async.cg.shared.global [%0], [%1], 16;" :: "r"(dst), "l"(src))
#define CP_COMMIT()        asm volatile("cp.async.commit_group;" ::: "memory")
#define CP_WAIT(n)         asm volatile("cp.async.wait_group %0;" :: "n"(n) : "memory")

#define APAD 36
#define ABUF (128*APAD)   // 4608 floats per tile buffer

// ---------------- K0: per-row LN stats of x ----------------
__global__ __launch_bounds__(256) void row_stats_x(const float* __restrict__ X) {
    int row = blockIdx.x * 8 + (threadIdx.x >> 5);
    int lane = threadIdx.x & 31;
    const float* p = X + (size_t)row * DD;
    float4 v0 = *(const float4*)(p + lane * 4);
    float4 v1 = *(const float4*)(p + 128 + lane * 4);
    float s  = v0.x + v0.y + v0.z + v0.w + v1.x + v1.y + v1.z + v1.w;
    float ss = v0.x*v0.x + v0.y*v0.y + v0.z*v0.z + v0.w*v0.w
             + v1.x*v1.x + v1.y*v1.y + v1.z*v1.z + v1.w*v1.w;
    #pragma unroll
    for (int o = 16; o > 0; o >>= 1) {
        s  += __shfl_xor_sync(0xffffffffu, s,  o);
        ss += __shfl_xor_sync(0xffffffffu, ss, o);
    }
    if (lane == 0) {
        float mu = s * (1.0f / DD);
        float var = ss * (1.0f / DD) - mu * mu;
        g_mean1[row] = mu;
        g_rstd1[row] = rsqrtf(var + 1e-5f);
    }
}

// ---------------- weight prep: transpose + tf32 hi/lo split ----------------
__global__ __launch_bounds__(256) void prep_w(const float* __restrict__ W,
                                              float* __restrict__ Wh,
                                              float* __restrict__ Wl) {
    int idx = blockIdx.x * 256 + threadIdx.x;   // 65536
    int k = idx >> 8, n = idx & 255;
    float w = W[idx];                            // W[k][n]
    float hi = tf32_rna(w);
    float lo = tf32_rna(w - hi);
    Wh[n * DD + k] = hi;
    Wl[n * DD + k] = lo;
}

// ---------------- mma.sync GEMM, pipelined ----------------
// MODE 0: A = LN(x_row),    out = gelu(.)        X3=1 (tf32x3 compensated)
// MODE 1: A = LN(lerp(xd)), out = gelu(.) + x    X3=0 (single tf32)
// CTA: 256 thr (8 warps, 4x2), tile 128(M) x 128(N), K chunks of 32.
// B double-buffered via cp.async; A gmem loads pipelined in registers.
template <int MODE, int X3>
__global__ __launch_bounds__(256, 2) void gemm_mma(
    const float* __restrict__ X,
    const float* __restrict__ Wh, const float* __restrict__ Wl,
    const float* __restrict__ bias,
    const float* __restrict__ ln_g, const float* __restrict__ ln_b,
    float* __restrict__ out)
{
    extern __shared__ float smem[];
    float* sg  = smem;                 // [256] ln gamma
    float* sbv = smem + 256;           // [256] ln beta
    float* sAh = smem + 512;           // [128][APAD]
    float* sAl = sAh + ABUF;           // X3 only
    float* sBh = smem + 512 + (X3 ? 2 : 1) * ABUF;   // [2][128][APAD]
    float* sBl = sBh + 2 * ABUF;       // X3 only, [2][128][APAD]

    const int tid  = threadIdx.x;
    const int wid  = tid >> 5;
    const int lane = tid & 31;
    const int m0   = blockIdx.x * 128;
    const int n0   = blockIdx.y * 128;
    const int warp_m = (wid & 3) * 32;
    const int warp_n = (wid >> 2) * 64;
    const int r  = lane >> 2;      // 0..7
    const int cq = lane & 3;       // 0..3

    // prologue: LN params to smem
    sg[tid]  = ln_g[tid];
    sbv[tid] = ln_b[tid];

    // chunk-invariant per-thread A-row constants (4 'it' slots)
    int   offA0[4], offA1[4];
    float muA[4], rsA[4], wA[4];
    #pragma unroll
    for (int it = 0; it < 4; ++it) {
        int f = tid + it * 256, row = f >> 3, fc = f & 7;
        int m = min(m0 + row, MROWS - 1);
        if (MODE == 0) {
            offA0[it] = m * DD + fc * 4;
            muA[it] = g_mean1[m]; rsA[it] = g_rstd1[m];
            wA[it] = 0.0f; offA1[it] = 0;
        } else {
            offA0[it] = g_off0[m] + fc * 4;
            offA1[it] = g_off1[m] + fc * 4;
            wA[it]  = g_wlerp[m];
            muA[it] = g_mean2[m]; rsA[it] = g_rstd2[m];
        }
    }

    float acc[2][8][4];
    #pragma unroll
    for (int i = 0; i < 2; i++)
        #pragma unroll
        for (int j = 0; j < 8; j++)
            #pragma unroll
            for (int q = 0; q < 4; q++) acc[i][j][q] = 0.0f;

    // fragment smem base pointers
    const float* paAh = sAh + (warp_m + r) * APAD + cq;
    const float* paAl = sAl + (warp_m + r) * APAD + cq;
    const float* paBh = sBh + (warp_n + r) * APAD + cq;
    const float* paBl = sBl + (warp_n + r) * APAD + cq;

    // stage B chunk kt into buffer buf (cp.async)
    auto stageB = [&](int kt, int buf) {
        #pragma unroll
        for (int it = 0; it < 4; ++it) {
            int f  = tid + it * 256;
            int nl = f >> 3;
            int fc = f & 7;
            int ng = n0 + nl;
            uint32_t dh = smem_u32(sBh + buf * ABUF + nl * APAD + fc * 4);
            CP_ASYNC(dh, Wh + (size_t)ng * DD + kt + fc * 4);
            if (X3) {
                uint32_t dl = smem_u32(sBl + buf * ABUF + nl * APAD + fc * 4);
                CP_ASYNC(dl, Wl + (size_t)ng * DD + kt + fc * 4);
            }
        }
    };
    // load A chunk kt into registers
    float4 v[4];
    auto ldA = [&](int kt) {
        #pragma unroll
        for (int it = 0; it < 4; ++it) {
            if (MODE == 0) {
                v[it] = *(const float4*)(X + offA0[it] + kt);
            } else {
                float w = wA[it];
                float4 a  = *(const float4*)(g_xd + offA0[it] + kt);
                float4 bq = *(const float4*)(g_xd + offA1[it] + kt);
                v[it].x = a.x + (bq.x - a.x) * w;
                v[it].y = a.y + (bq.y - a.y) * w;
                v[it].z = a.z + (bq.z - a.z) * w;
                v[it].w = a.w + (bq.w - a.w) * w;
            }
        }
    };

    stageB(0, 0);
    CP_COMMIT();
    ldA(0);

    #pragma unroll 2
    for (int c = 0; c < 8; ++c) {
        const int kt = c * 32;
        // ---- A math + STS (v holds chunk c) ----
        #pragma unroll
        for (int it = 0; it < 4; ++it) {
            int f = tid + it * 256, row = f >> 3, fc = f & 7;
            float4 gg = *(const float4*)(sg  + kt + fc * 4);
            float4 bb = *(const float4*)(sbv + kt + fc * 4);
            float a0 = (v[it].x - muA[it]) * rsA[it] * gg.x + bb.x;
            float a1 = (v[it].y - muA[it]) * rsA[it] * gg.y + bb.y;
            float a2 = (v[it].z - muA[it]) * rsA[it] * gg.z + bb.z;
            float a3 = (v[it].w - muA[it]) * rsA[it] * gg.w + bb.w;
            float h0 = tf32_rna(a0), h1 = tf32_rna(a1);
            float h2 = tf32_rna(a2), h3 = tf32_rna(a3);
            *(float4*)(sAh + row * APAD + fc * 4) = make_float4(h0, h1, h2, h3);
            if (X3)
                *(float4*)(sAl + row * APAD + fc * 4) = make_float4(
                    tf32_rna(a0 - h0), tf32_rna(a1 - h1),
                    tf32_rna(a2 - h2), tf32_rna(a3 - h3));
        }
        if (c < 7) { stageB(kt + 32, (c + 1) & 1); CP_COMMIT(); }
        if (c < 7) CP_WAIT(1); else CP_WAIT(0);
        __syncthreads();
        if (c < 7) ldA(kt + 32);   // LDG hidden behind MMAs below

        const float* pBh = paBh + (c & 1) * ABUF;
        const float* pBl = paBl + (c & 1) * ABUF;
        #pragma unroll
        for (int ks = 0; ks < 4; ++ks) {
            const int ko = ks * 8;
            float ah[2][4], al[2][4];
            #pragma unroll
            for (int mt = 0; mt < 2; ++mt) {
                const float* p = paAh + mt * 16 * APAD + ko;
                ah[mt][0] = p[0];
                ah[mt][1] = p[8 * APAD];
                ah[mt][2] = p[4];
                ah[mt][3] = p[8 * APAD + 4];
                if (X3) {
                    const float* q = paAl + mt * 16 * APAD + ko;
                    al[mt][0] = q[0];
                    al[mt][1] = q[8 * APAD];
                    al[mt][2] = q[4];
                    al[mt][3] = q[8 * APAD + 4];
                }
            }
            #pragma unroll
            for (int nt = 0; nt < 8; ++nt) {
                float bh[2];
                const float* pb = pBh + nt * 8 * APAD + ko;
                bh[0] = pb[0]; bh[1] = pb[4];
                mma1688(acc[0][nt], ah[0], bh);
                mma1688(acc[1][nt], ah[1], bh);
                if (X3) {
                    mma1688(acc[0][nt], al[0], bh);
                    mma1688(acc[1][nt], al[1], bh);
                    float bl[2];
                    const float* pl = pBl + nt * 8 * APAD + ko;
                    bl[0] = pl[0]; bl[1] = pl[4];
                    mma1688(acc[0][nt], ah[0], bl);
                    mma1688(acc[1][nt], ah[1], bl);
                }
            }
        }
        __syncthreads();
    }

    // ---- epilogue: bias + gelu (+residual) -> gmem ----
    #pragma unroll
    for (int mt = 0; mt < 2; ++mt) {
        int mrow = m0 + warp_m + mt * 16 + r;
        #pragma unroll
        for (int nt = 0; nt < 8; ++nt) {
            int n = n0 + warp_n + nt * 8 + 2 * cq;
            float2 bi = *(const float2*)(bias + n);
            if (mrow < MROWS) {
                float o0 = gelu_f(acc[mt][nt][0] + bi.x);
                float o1 = gelu_f(acc[mt][nt][1] + bi.y);
                if (MODE == 1) {
                    float2 xr = *(const float2*)(X + (size_t)mrow * DD + n);
                    o0 += xr.x; o1 += xr.y;
                }
                *(float2*)(out + (size_t)mrow * DD + n) = make_float2(o0, o1);
            }
            int mrow2 = mrow + 8;
            if (mrow2 < MROWS) {
                float o2 = gelu_f(acc[mt][nt][2] + bi.x);
                float o3 = gelu_f(acc[mt][nt][3] + bi.y);
                if (MODE == 1) {
                    float2 xr = *(const float2*)(X + (size_t)mrow2 * DD + n);
                    o2 += xr.x; o3 += xr.y;
                }
                *(float2*)(out + (size_t)mrow2 * DD + n) = make_float2(o2, o3);
            }
        }
    }
}

// ---------------- K2a: adaptive avg pool T -> T_RED ----------------
__global__ __launch_bounds__(256) void pool_kernel() {
    int id = blockIdx.x;               // b * TR * JJ + r * JJ + j
    int j = id % JJ;
    int r = (id / JJ) % TR;
    int b = id / (JJ * TR);
    int s = (r * TT) / TR;
    int e = ((r + 1) * TT + TR - 1) / TR;
    int c = threadIdx.x;
    float acc = 0.0f;
    for (int t = s; t < e; ++t)
        acc += g_h[((size_t)((b * TT + t) * JJ + j)) * DD + c];
    g_xd[((size_t)((b * TR + r) * JJ + j)) * DD + c] = acc / (float)(e - s);
}

// ---------------- K2b: mean over J ----------------
__global__ __launch_bounds__(256) void pooled_mean_kernel() {
    int id = blockIdx.x;               // b * TR + r
    int c = threadIdx.x;
    float acc = 0.0f;
    #pragma unroll
    for (int j = 0; j < JJ; ++j)
        acc += g_xd[((size_t)(id * JJ + j)) * DD + c];
    g_pm[(size_t)id * DD + c] = acc * (1.0f / JJ);
}

// ---------------- K3: scorer + top-k (one block per batch, w1 in smem) ----------------
__global__ __launch_bounds__(128) void scorer_topk(
    const float* __restrict__ w1, const float* __restrict__ b1,
    const float* __restrict__ w2, const float* __restrict__ b2)
{
    extern __shared__ float sw1[];      // [DD*DH] = 64KB
    __shared__ float spm[DD];
    __shared__ float red[DH];
    __shared__ float scores[TR];
    __shared__ int   sel[TR];
    int b = blockIdx.x, tid = threadIdx.x;

    for (int i = tid; i < DD * DH; i += 128) sw1[i] = w1[i];
    float b1v = b1[tid];
    float w2v = w2[tid];
    float b2v = b2[0];
    __syncthreads();

    for (int r = 0; r < TR; ++r) {
        spm[tid]        = g_pm[((size_t)(b * TR + r)) * DD + tid];
        spm[tid + 128]  = g_pm[((size_t)(b * TR + r)) * DD + tid + 128];
        __syncthreads();
        float acc = b1v;
        #pragma unroll 8
        for (int c = 0; c < DD; ++c)
            acc = fmaf(spm[c], sw1[c * DH + tid], acc);
        red[tid] = gelu_f(acc) * w2v;
        __syncthreads();
        #pragma unroll
        for (int s = 64; s > 0; s >>= 1) {
            if (tid < s) red[tid] += red[tid + s];
            __syncthreads();
        }
        if (tid == 0)
            scores[r] = 1.0f / (1.0f + expf(-(red[0] + b2v)));
        __syncthreads();
    }
    if (tid < TR) {
        float s = scores[tid];
        int rank = 0;
        for (int q = 0; q < TR; ++q) {
            float sq = scores[q];
            rank += (sq > s) || (sq == s && q < tid);
        }
        sel[tid] = (rank < KSEL) ? 1 : 0;
    }
    __syncthreads();
    if (tid == 0) {
        int pos = 0;
        for (int r = 0; r < TR; ++r)
            if (sel[r]) g_topidx[b * KSEL + (pos++)] = r;
    }
}

// ---------------- K4pre: per-row lerp offsets/weight + LN stats of 'up' ----------------
__global__ __launch_bounds__(256) void up_pre() {
    int row  = blockIdx.x * 8 + (threadIdx.x >> 5);
    int lane = threadIdx.x & 31;
    int b   = row / TJ;
    int rem = row % TJ;
    int t = rem / JJ;
    int j = rem % JJ;

    const float scale = (float)(30.0 / 243.0);
    float src = (t + 0.5f) * scale - 0.5f;
    src = fminf(fmaxf(src, 0.0f), (float)(KSEL - 1));
    int x0 = (int)src;
    int x1 = min(x0 + 1, KSEL - 1);
    float w = src - (float)x0;
    int i0 = g_topidx[b * KSEL + x0];
    int i1 = g_topidx[b * KSEL + x1];
    int off0 = ((b * TR + i0) * JJ + j) * DD;
    int off1 = ((b * TR + i1) * JJ + j) * DD;

    float s = 0.0f, ss = 0.0f;
    #pragma unroll
    for (int h = 0; h < 2; ++h) {
        int c = h * 128 + lane * 4;
        float4 a  = *(const float4*)(g_xd + off0 + c);
        float4 bq = *(const float4*)(g_xd + off1 + c);
        float v0 = a.x + (bq.x - a.x) * w;
        float v1 = a.y + (bq.y - a.y) * w;
        float v2 = a.z + (bq.z - a.z) * w;
        float v3 = a.w + (bq.w - a.w) * w;
        s  += v0 + v1 + v2 + v3;
        ss += v0*v0 + v1*v1 + v2*v2 + v3*v3;
    }
    #pragma unroll
    for (int o = 16; o > 0; o >>= 1) {
        s  += __shfl_xor_sync(0xffffffffu, s,  o);
        ss += __shfl_xor_sync(0xffffffffu, ss, o);
    }
    if (lane == 0) {
        float mu  = s * (1.0f / DD);
        float var = ss * (1.0f / DD) - mu * mu;
        g_mean2[row] = mu;
        g_rstd2[row] = rsqrtf(var + 1e-5f);
        g_off0[row] = off0;
        g_off1[row] = off1;
        g_wlerp[row] = w;
    }
}

// ---------------- launch ----------------
#define SMEM_X3 ((512 + 6 * ABUF) * 4)   // 112640 B
#define SMEM_X1 ((512 + 3 * ABUF) * 4)   // 57344 B
#define SMEM_SC (DD * DH * 4)            // 65536 B

extern "C" void kernel_launch(void* const* d_in, const int* in_sizes, int n_in,
                              void* d_out, int out_size) {
    const float* x       = (const float*)d_in[0];
    const float* fp_g    = (const float*)d_in[1];
    const float* fp_b    = (const float*)d_in[2];
    const float* fp_w    = (const float*)d_in[3];
    const float* fp_bias = (const float*)d_in[4];
    const float* sc_w1   = (const float*)d_in[5];
    const float* sc_b1   = (const float*)d_in[6];
    const float* sc_w2   = (const float*)d_in[7];
    const float* sc_b2   = (const float*)d_in[8];
    const float* op_g    = (const float*)d_in[9];
    const float* op_b    = (const float*)d_in[10];
    const float* op_w    = (const float*)d_in[11];
    const float* op_bias = (const float*)d_in[12];
    float* out = (float*)d_out;

    float *h_ptr, *w0h, *w0l, *w1h, *w1l;
    cudaGetSymbolAddress((void**)&h_ptr, g_h);
    cudaGetSymbolAddress((void**)&w0h, g_wt0h);
    cudaGetSymbolAddress((void**)&w0l, g_wt0l);
    cudaGetSymbolAddress((void**)&w1h, g_wt1h);
    cudaGetSymbolAddress((void**)&w1l, g_wt1l);

    cudaFuncSetAttribute(gemm_mma<0,1>, cudaFuncAttributeMaxDynamicSharedMemorySize, SMEM_X3);
    cudaFuncSetAttribute(gemm_mma<1,0>, cudaFuncAttributeMaxDynamicSharedMemorySize, SMEM_X1);
    cudaFuncSetAttribute(scorer_topk, cudaFuncAttributeMaxDynamicSharedMemorySize, SMEM_SC);

    dim3 ggrid(MTILES, 2);
    prep_w<<<256, 256>>>(fp_w, w0h, w0l);
    prep_w<<<256, 256>>>(op_w, w1h, w1l);
    row_stats_x<<<MROWS / 8, 256>>>(x);
    gemm_mma<0,1><<<ggrid, 256, SMEM_X3>>>(x, w0h, w0l, fp_bias, fp_g, fp_b, h_ptr);
    pool_kernel<<<BB * TR * JJ, 256>>>();
    pooled_mean_kernel<<<BB * TR, 256>>>();
    scorer_topk<<<BB, 128, SMEM_SC>>>(sc_w1, sc_b1, sc_w2, sc_b2);
    up_pre<<<MROWS / 8, 256>>>();
    gemm_mma<1,0><<<ggrid, 256, SMEM_X1>>>(x, w1h, w1l, op_bias, op_g, op_b, out);
}

// round 5
// speedup vs baseline: 1.9993x; 1.1874x over previous
#include <cuda_runtime.h>
#include <cuda_bf16.h>
#include <math.h>
#include <stdint.h>

// ---------------- problem constants ----------------
#define BB 64
#define TT 243
#define JJ 17
#define DD 256
#define DH 128
#define TR 60
#define KSEL 30
#define MROWS (BB*TT*JJ)       // 264384 = 64 * 4131
#define TJ (TT*JJ)             // 4131
#define MTILES (MROWS/64)      // 4131 (exact)

// ---------------- scratch (device globals; no allocs allowed) ----------------
__device__ float g_h[(size_t)MROWS*DD];          // 270.7 MB: fp-stage output
__device__ float g_xd[(size_t)BB*TR*JJ*DD];      // 66.8 MB: pooled
__device__ float g_pm[(size_t)BB*TR*DD];         // pooled mean over J
__device__ float g_mean1[MROWS], g_rstd1[MROWS];
__device__ float g_mean2[MROWS], g_rstd2[MROWS];
__device__ int   g_off0[MROWS], g_off1[MROWS];
__device__ float g_wlerp[MROWS];
__device__ int   g_topidx[BB*KSEL];
__device__ __nv_bfloat16 g_w0h[DD*DD], g_w0l[DD*DD];   // fp_w^T bf16 hi/lo
__device__ __nv_bfloat16 g_w1h[DD*DD], g_w1l[DD*DD];   // op_w^T bf16 hi/lo

__device__ __forceinline__ float gelu_f(float x) {
    return 0.5f * x * (1.0f + erff(x * 0.70710678118654752f));
}
__device__ __forceinline__ uint32_t smem_u32(const void* p) {
    uint32_t a;
    asm("{ .reg .u64 t; cvta.to.shared.u64 t, %1; cvt.u32.u64 %0, t; }" : "=r"(a) : "l"(p));
    return a;
}
// mma m16n8k16 bf16 (sm_80+, safe on non-"a" target)
__device__ __forceinline__ void mma_bf16(float* d, const uint32_t* a,
                                         uint32_t b0, uint32_t b1) {
    asm volatile(
        "mma.sync.aligned.m16n8k16.row.col.f32.bf16.bf16.f32 "
        "{%0,%1,%2,%3}, {%4,%5,%6,%7}, {%8,%9}, {%0,%1,%2,%3};"
        : "+f"(d[0]), "+f"(d[1]), "+f"(d[2]), "+f"(d[3])
        : "r"(a[0]), "r"(a[1]), "r"(a[2]), "r"(a[3]), "r"(b0), "r"(b1));
}
#define CP_ASYNC(dst, src) asm volatile("cp.async.cg.shared.global [%0], [%1], 16;" :: "r"(dst), "l"(src))
#define CP_COMMIT()        asm volatile("cp.async.commit_group;" ::: "memory")
#define CP_WAIT(n)         asm volatile("cp.async.wait_group %0;" :: "n"(n) : "memory")

// smem layouts (u32 units). stride 20 => bank-conflict-free for frag loads.
#define ASTR 20
#define AB   (64*ASTR)     // 1280 u32 per A half
#define BSTR 20
#define BB_  (256*BSTR)    // 5120 u32 per B buffer half

// ---------------- K0: per-row LN stats of x ----------------
__global__ __launch_bounds__(256) void row_stats_x(const float* __restrict__ X) {
    int row = blockIdx.x * 8 + (threadIdx.x >> 5);
    int lane = threadIdx.x & 31;
    const float* p = X + (size_t)row * DD;
    float4 v0 = *(const float4*)(p + lane * 4);
    float4 v1 = *(const float4*)(p + 128 + lane * 4);
    float s  = v0.x + v0.y + v0.z + v0.w + v1.x + v1.y + v1.z + v1.w;
    float ss = v0.x*v0.x + v0.y*v0.y + v0.z*v0.z + v0.w*v0.w
             + v1.x*v1.x + v1.y*v1.y + v1.z*v1.z + v1.w*v1.w;
    #pragma unroll
    for (int o = 16; o > 0; o >>= 1) {
        s  += __shfl_xor_sync(0xffffffffu, s,  o);
        ss += __shfl_xor_sync(0xffffffffu, ss, o);
    }
    if (lane == 0) {
        float mu = s * (1.0f / DD);
        float var = ss * (1.0f / DD) - mu * mu;
        g_mean1[row] = mu;
        g_rstd1[row] = rsqrtf(var + 1e-5f);
    }
}

// ---------------- weight prep: transpose + bf16 hi/lo split ----------------
__global__ __launch_bounds__(256) void prep_w(const float* __restrict__ W,
                                              __nv_bfloat16* __restrict__ Wh,
                                              __nv_bfloat16* __restrict__ Wl) {
    int idx = blockIdx.x * 256 + threadIdx.x;   // 65536
    int k = idx >> 8, n = idx & 255;
    float w = W[idx];                            // W[k][n]
    __nv_bfloat16 hi = __float2bfloat16(w);
    __nv_bfloat16 lo = __float2bfloat16(w - __bfloat162float(hi));
    Wh[n * DD + k] = hi;
    Wl[n * DD + k] = lo;
}

// ---------------- bf16x3 mma GEMM: LN(A) @ W^T + bias -> gelu (+residual) ----------------
// MODE 0: A = LN(x_row),    out = gelu(.)
// MODE 1: A = LN(lerp(xd)), out = gelu(.) + x
// CTA: 256 thr (8 warps, 2Mx4N), tile 64(M) x 256(N), K chunks of 32 (2 k16 steps).
template <int MODE>
__global__ __launch_bounds__(256, 2) void gemm_bf16(
    const float* __restrict__ X,
    const __nv_bfloat16* __restrict__ Wh, const __nv_bfloat16* __restrict__ Wl,
    const float* __restrict__ bias,
    const float* __restrict__ ln_g, const float* __restrict__ ln_b,
    float* __restrict__ out)
{
    extern __shared__ float smem[];
    float* sg  = smem;                 // [256]
    float* sbv = smem + 256;           // [256]
    uint32_t* sAh = (uint32_t*)(smem + 512);
    uint32_t* sAl = sAh + AB;
    uint32_t* sBh = sAl + AB;          // [2][256][BSTR]
    uint32_t* sBl = sBh + 2 * BB_;     // [2][256][BSTR]

    const int tid  = threadIdx.x;
    const int wid  = tid >> 5;
    const int lane = tid & 31;
    const int m0   = blockIdx.x * 64;
    const int warp_m = (wid & 1) * 32;
    const int warp_n = (wid >> 1) * 64;
    const int r  = lane >> 2;      // 0..7
    const int cq = lane & 3;       // 0..3

    sg[tid]  = ln_g[tid];
    sbv[tid] = ln_b[tid];

    // per-thread A-row constants: 2 slots (rows tid>>3 and 32+tid>>3)
    int   offA0[2], offA1[2];
    float muA[2], rsA[2], wA[2];
    const int aq = tid & 7;            // k-quad within chunk (0..7)
    #pragma unroll
    for (int it = 0; it < 2; ++it) {
        int row = (tid >> 3) + it * 32;
        int m = m0 + row;
        if (MODE == 0) {
            offA0[it] = m * DD + aq * 4;
            muA[it] = g_mean1[m]; rsA[it] = g_rstd1[m];
            wA[it] = 0.0f; offA1[it] = 0;
        } else {
            offA0[it] = g_off0[m] + aq * 4;
            offA1[it] = g_off1[m] + aq * 4;
            wA[it]  = g_wlerp[m];
            muA[it] = g_mean2[m]; rsA[it] = g_rstd2[m];
        }
    }

    float acc[2][8][4];
    #pragma unroll
    for (int i = 0; i < 2; i++)
        #pragma unroll
        for (int j = 0; j < 8; j++)
            #pragma unroll
            for (int q = 0; q < 4; q++) acc[i][j][q] = 0.0f;

    const uint32_t* paAh = sAh + (warp_m + r) * ASTR + cq;
    const uint32_t* paAl = sAl + (warp_m + r) * ASTR + cq;
    const uint32_t* paBh = sBh + (warp_n + r) * BSTR + cq;
    const uint32_t* paBl = sBl + (warp_n + r) * BSTR + cq;

    // stage B chunk kt -> buffer buf (cp.async): 256 n-rows x 32 k bf16
    auto stageB = [&](int kt, int buf) {
        #pragma unroll
        for (int it = 0; it < 4; ++it) {
            int f = tid + it * 256;        // 0..1023
            int n = f >> 2;                // 0..255
            int q = f & 3;                 // 16B piece (8 bf16)
            uint32_t dh = smem_u32(sBh + buf * BB_ + n * BSTR + q * 4);
            CP_ASYNC(dh, Wh + (size_t)n * DD + kt + q * 8);
            uint32_t dl = smem_u32(sBl + buf * BB_ + n * BSTR + q * 4);
            CP_ASYNC(dl, Wl + (size_t)n * DD + kt + q * 8);
        }
    };
    float4 v[2];
    auto ldA = [&](int kt) {
        #pragma unroll
        for (int it = 0; it < 2; ++it) {
            if (MODE == 0) {
                v[it] = *(const float4*)(X + offA0[it] + kt);
            } else {
                float w = wA[it];
                float4 a  = *(const float4*)(g_xd + offA0[it] + kt);
                float4 bq = *(const float4*)(g_xd + offA1[it] + kt);
                v[it].x = a.x + (bq.x - a.x) * w;
                v[it].y = a.y + (bq.y - a.y) * w;
                v[it].z = a.z + (bq.z - a.z) * w;
                v[it].w = a.w + (bq.w - a.w) * w;
            }
        }
    };

    stageB(0, 0);
    CP_COMMIT();
    ldA(0);

    #pragma unroll 2
    for (int c = 0; c < 8; ++c) {
        const int kt = c * 32;
        // ---- A math + STS (v holds chunk c) ----
        #pragma unroll
        for (int it = 0; it < 2; ++it) {
            int row = (tid >> 3) + it * 32;
            float4 gg = *(const float4*)(sg  + kt + aq * 4);
            float4 bb = *(const float4*)(sbv + kt + aq * 4);
            float a0 = (v[it].x - muA[it]) * rsA[it] * gg.x + bb.x;
            float a1 = (v[it].y - muA[it]) * rsA[it] * gg.y + bb.y;
            float a2 = (v[it].z - muA[it]) * rsA[it] * gg.z + bb.z;
            float a3 = (v[it].w - muA[it]) * rsA[it] * gg.w + bb.w;
            __nv_bfloat162 h01 = __floats2bfloat162_rn(a0, a1);
            __nv_bfloat162 h23 = __floats2bfloat162_rn(a2, a3);
            __nv_bfloat162 l01 = __floats2bfloat162_rn(
                a0 - __bfloat162float(h01.x), a1 - __bfloat162float(h01.y));
            __nv_bfloat162 l23 = __floats2bfloat162_rn(
                a2 - __bfloat162float(h23.x), a3 - __bfloat162float(h23.y));
            uint32_t* dh = sAh + row * ASTR + aq * 2;
            dh[0] = *(uint32_t*)&h01; dh[1] = *(uint32_t*)&h23;
            uint32_t* dl = sAl + row * ASTR + aq * 2;
            dl[0] = *(uint32_t*)&l01; dl[1] = *(uint32_t*)&l23;
        }
        if (c < 7) { stageB(kt + 32, (c + 1) & 1); CP_COMMIT(); CP_WAIT(1); }
        else       { CP_WAIT(0); }
        __syncthreads();
        if (c < 7) ldA(kt + 32);   // hidden behind MMAs

        const uint32_t* pBh = paBh + (c & 1) * BB_;
        const uint32_t* pBl = paBl + (c & 1) * BB_;
        #pragma unroll
        for (int ks = 0; ks < 2; ++ks) {
            const int ko = ks * 8;
            uint32_t ah[2][4], al[2][4];
            #pragma unroll
            for (int mt = 0; mt < 2; ++mt) {
                const uint32_t* p = paAh + mt * 16 * ASTR + ko;
                ah[mt][0] = p[0]; ah[mt][1] = p[8 * ASTR];
                ah[mt][2] = p[4]; ah[mt][3] = p[8 * ASTR + 4];
                const uint32_t* q = paAl + mt * 16 * ASTR + ko;
                al[mt][0] = q[0]; al[mt][1] = q[8 * ASTR];
                al[mt][2] = q[4]; al[mt][3] = q[8 * ASTR + 4];
            }
            #pragma unroll
            for (int nt = 0; nt < 8; ++nt) {
                const uint32_t* pb = pBh + nt * 8 * BSTR + ko;
                uint32_t bh0 = pb[0], bh1 = pb[4];
                const uint32_t* pl = pBl + nt * 8 * BSTR + ko;
                uint32_t bl0 = pl[0], bl1 = pl[4];
                mma_bf16(acc[0][nt], ah[0], bh0, bh1);
                mma_bf16(acc[1][nt], ah[1], bh0, bh1);
                mma_bf16(acc[0][nt], ah[0], bl0, bl1);
                mma_bf16(acc[1][nt], ah[1], bl0, bl1);
                mma_bf16(acc[0][nt], al[0], bh0, bh1);
                mma_bf16(acc[1][nt], al[1], bh0, bh1);
            }
        }
        __syncthreads();
    }

    // ---- epilogue: bias + gelu (+residual) -> gmem ----
    #pragma unroll
    for (int mt = 0; mt < 2; ++mt) {
        int mrow = m0 + warp_m + mt * 16 + r;
        #pragma unroll
        for (int nt = 0; nt < 8; ++nt) {
            int n = warp_n + nt * 8 + 2 * cq;
            float2 bi = *(const float2*)(bias + n);
            {
                float o0 = gelu_f(acc[mt][nt][0] + bi.x);
                float o1 = gelu_f(acc[mt][nt][1] + bi.y);
                if (MODE == 1) {
                    float2 xr = *(const float2*)(X + (size_t)mrow * DD + n);
                    o0 += xr.x; o1 += xr.y;
                }
                *(float2*)(out + (size_t)mrow * DD + n) = make_float2(o0, o1);
            }
            {
                int m2 = mrow + 8;
                float o2 = gelu_f(acc[mt][nt][2] + bi.x);
                float o3 = gelu_f(acc[mt][nt][3] + bi.y);
                if (MODE == 1) {
                    float2 xr = *(const float2*)(X + (size_t)m2 * DD + n);
                    o2 += xr.x; o3 += xr.y;
                }
                *(float2*)(out + (size_t)m2 * DD + n) = make_float2(o2, o3);
            }
        }
    }
}

// ---------------- K2a: adaptive avg pool T -> T_RED ----------------
__global__ __launch_bounds__(256) void pool_kernel() {
    int id = blockIdx.x;
    int j = id % JJ;
    int r = (id / JJ) % TR;
    int b = id / (JJ * TR);
    int s = (r * TT) / TR;
    int e = ((r + 1) * TT + TR - 1) / TR;
    int c = threadIdx.x;
    float acc = 0.0f;
    for (int t = s; t < e; ++t)
        acc += g_h[((size_t)((b * TT + t) * JJ + j)) * DD + c];
    g_xd[((size_t)((b * TR + r) * JJ + j)) * DD + c] = acc / (float)(e - s);
}

// ---------------- K2b: mean over J ----------------
__global__ __launch_bounds__(256) void pooled_mean_kernel() {
    int id = blockIdx.x;
    int c = threadIdx.x;
    float acc = 0.0f;
    #pragma unroll
    for (int j = 0; j < JJ; ++j)
        acc += g_xd[((size_t)(id * JJ + j)) * DD + c];
    g_pm[(size_t)id * DD + c] = acc * (1.0f / JJ);
}

// ---------------- K3: scorer + top-k ----------------
__global__ __launch_bounds__(128) void scorer_topk(
    const float* __restrict__ w1, const float* __restrict__ b1,
    const float* __restrict__ w2, const float* __restrict__ b2)
{
    extern __shared__ float sw1[];      // [DD*DH]
    __shared__ float spm[DD];
    __shared__ float red[DH];
    __shared__ float scores[TR];
    __shared__ int   sel[TR];
    int b = blockIdx.x, tid = threadIdx.x;

    for (int i = tid; i < DD * DH; i += 128) sw1[i] = w1[i];
    float b1v = b1[tid];
    float w2v = w2[tid];
    float b2v = b2[0];
    __syncthreads();

    for (int r = 0; r < TR; ++r) {
        spm[tid]        = g_pm[((size_t)(b * TR + r)) * DD + tid];
        spm[tid + 128]  = g_pm[((size_t)(b * TR + r)) * DD + tid + 128];
        __syncthreads();
        float acc = b1v;
        #pragma unroll 8
        for (int c = 0; c < DD; ++c)
            acc = fmaf(spm[c], sw1[c * DH + tid], acc);
        red[tid] = gelu_f(acc) * w2v;
        __syncthreads();
        #pragma unroll
        for (int s = 64; s > 0; s >>= 1) {
            if (tid < s) red[tid] += red[tid + s];
            __syncthreads();
        }
        if (tid == 0)
            scores[r] = 1.0f / (1.0f + expf(-(red[0] + b2v)));
        __syncthreads();
    }
    if (tid < TR) {
        float s = scores[tid];
        int rank = 0;
        for (int q = 0; q < TR; ++q) {
            float sq = scores[q];
            rank += (sq > s) || (sq == s && q < tid);
        }
        sel[tid] = (rank < KSEL) ? 1 : 0;
    }
    __syncthreads();
    if (tid == 0) {
        int pos = 0;
        for (int r = 0; r < TR; ++r)
            if (sel[r]) g_topidx[b * KSEL + (pos++)] = r;
    }
}

// ---------------- K4pre: per-row lerp offsets/weight + LN stats of 'up' ----------------
__global__ __launch_bounds__(256) void up_pre() {
    int row  = blockIdx.x * 8 + (threadIdx.x >> 5);
    int lane = threadIdx.x & 31;
    int b   = row / TJ;
    int rem = row % TJ;
    int t = rem / JJ;
    int j = rem % JJ;

    const float scale = (float)(30.0 / 243.0);
    float src = (t + 0.5f) * scale - 0.5f;
    src = fminf(fmaxf(src, 0.0f), (float)(KSEL - 1));
    int x0 = (int)src;
    int x1 = min(x0 + 1, KSEL - 1);
    float w = src - (float)x0;
    int i0 = g_topidx[b * KSEL + x0];
    int i1 = g_topidx[b * KSEL + x1];
    int off0 = ((b * TR + i0) * JJ + j) * DD;
    int off1 = ((b * TR + i1) * JJ + j) * DD;

    float s = 0.0f, ss = 0.0f;
    #pragma unroll
    for (int h = 0; h < 2; ++h) {
        int c = h * 128 + lane * 4;
        float4 a  = *(const float4*)(g_xd + off0 + c);
        float4 bq = *(const float4*)(g_xd + off1 + c);
        float v0 = a.x + (bq.x - a.x) * w;
        float v1 = a.y + (bq.y - a.y) * w;
        float v2 = a.z + (bq.z - a.z) * w;
        float v3 = a.w + (bq.w - a.w) * w;
        s  += v0 + v1 + v2 + v3;
        ss += v0*v0 + v1*v1 + v2*v2 + v3*v3;
    }
    #pragma unroll
    for (int o = 16; o > 0; o >>= 1) {
        s  += __shfl_xor_sync(0xffffffffu, s,  o);
        ss += __shfl_xor_sync(0xffffffffu, ss, o);
    }
    if (lane == 0) {
        float mu  = s * (1.0f / DD);
        float var = ss * (1.0f / DD) - mu * mu;
        g_mean2[row] = mu;
        g_rstd2[row] = rsqrtf(var + 1e-5f);
        g_off0[row] = off0;
        g_off1[row] = off1;
        g_wlerp[row] = w;
    }
}

// ---------------- launch ----------------
#define SMEM_G ((512 + 2*AB + 4*BB_) * 4)   // 94208 B
#define SMEM_SC (DD * DH * 4)               // 65536 B

extern "C" void kernel_launch(void* const* d_in, const int* in_sizes, int n_in,
                              void* d_out, int out_size) {
    const float* x       = (const float*)d_in[0];
    const float* fp_g    = (const float*)d_in[1];
    const float* fp_b    = (const float*)d_in[2];
    const float* fp_w    = (const float*)d_in[3];
    const float* fp_bias = (const float*)d_in[4];
    const float* sc_w1   = (const float*)d_in[5];
    const float* sc_b1   = (const float*)d_in[6];
    const float* sc_w2   = (const float*)d_in[7];
    const float* sc_b2   = (const float*)d_in[8];
    const float* op_g    = (const float*)d_in[9];
    const float* op_b    = (const float*)d_in[10];
    const float* op_w    = (const float*)d_in[11];
    const float* op_bias = (const float*)d_in[12];
    float* out = (float*)d_out;

    float* h_ptr;
    __nv_bfloat16 *w0h, *w0l, *w1h, *w1l;
    cudaGetSymbolAddress((void**)&h_ptr, g_h);
    cudaGetSymbolAddress((void**)&w0h, g_w0h);
    cudaGetSymbolAddress((void**)&w0l, g_w0l);
    cudaGetSymbolAddress((void**)&w1h, g_w1h);
    cudaGetSymbolAddress((void**)&w1l, g_w1l);

    cudaFuncSetAttribute(gemm_bf16<0>, cudaFuncAttributeMaxDynamicSharedMemorySize, SMEM_G);
    cudaFuncSetAttribute(gemm_bf16<1>, cudaFuncAttributeMaxDynamicSharedMemorySize, SMEM_G);
    cudaFuncSetAttribute(scorer_topk, cudaFuncAttributeMaxDynamicSharedMemorySize, SMEM_SC);

    prep_w<<<256, 256>>>(fp_w, w0h, w0l);
    prep_w<<<256, 256>>>(op_w, w1h, w1l);
    row_stats_x<<<MROWS / 8, 256>>>(x);
    gemm_bf16<0><<<MTILES, 256, SMEM_G>>>(x, w0h, w0l, fp_bias, fp_g, fp_b, h_ptr);
    pool_kernel<<<BB * TR * JJ, 256>>>();
    pooled_mean_kernel<<<BB * TR, 256>>>();
    scorer_topk<<<BB, 128, SMEM_SC>>>(sc_w1, sc_b1, sc_w2, sc_b2);
    up_pre<<<MROWS / 8, 256>>>();
    gemm_bf16<1><<<MTILES, 256, SMEM_G>>>(x, w1h, w1l, op_bias, op_g, op_b, out);
}